// round 8
// baseline (speedup 1.0000x reference)
#include <cuda_runtime.h>
#include <cuda_fp16.h>
#include <cstdint>

#define SEQ   16384
#define HID   2048
#define EMB   512
#define NCHR  128
#define FAN   2560
#define NCTA  148
#define TPB   1024

// smem layout (bytes)
#define S_W_OFF   0
#define HHI_OFF   221184              // 54 rows * 4096
#define HLO_OFF   225280
#define PART_OFF  229376              // float[4][8][16]
#define SMEM_BYTES 231424

__device__ unsigned int g_ctr;
__device__ __align__(16) float g_h[2][HID];
__device__ __align__(16) __half g_w16[4 * HID * HID];     // fp16 Wh, 32MB
__device__ __align__(16) float g_gx[NCHR * 4 * HID];
__device__ __align__(16) float g_embT[EMB * NCHR];
__device__ __align__(16) float g_hist[(size_t)SEQ * HID];

__device__ __forceinline__ float sigf(float x) { return 1.f / (1.f + __expf(-x)); }
__device__ __forceinline__ float tanh_f(float x) {
    x = fminf(fmaxf(x, -15.f), 15.f);
    float e = __expf(2.f * x);
    return (e - 1.f) / (e + 1.f);
}
__device__ __forceinline__ uint32_t pack_h2(__half a, __half b) {
    return (uint32_t)__half_as_ushort(a) | ((uint32_t)__half_as_ushort(b) << 16);
}
__device__ __forceinline__ float2 h22f2(uint32_t u) {
    __half2 h = *reinterpret_cast<__half2*>(&u);
    return __half22float2(h);
}

__global__ void embTk(const float* __restrict__ emb) {
    int i = blockIdx.x * blockDim.x + threadIdx.x;
    if (i < EMB * NCHR) {
        int k = i / NCHR, c = i % NCHR;
        g_embT[(size_t)k * NCHR + c] = emb[(size_t)c * EMB + k];
    }
}

// fp16 weight conversion + per-call reset (keeps lstm_persist at launch idx 3)
__global__ void w16k(const float* __restrict__ Wf, const float* __restrict__ Wi,
                     const float* __restrict__ Wg, const float* __restrict__ Wo) {
    if (blockIdx.x < 8) {
        int i = blockIdx.x * 256 + threadIdx.x;
        g_h[0][i] = 0.f; g_h[1][i] = 0.f;
        if (i == 0) g_ctr = 0u;
    }
    int rho = blockIdx.x;
    int g = rho >> 11, j = rho & 2047;
    const float* W = (g == 0) ? Wf : (g == 1) ? Wi : (g == 2) ? Wg : Wo;
    const float* row = W + (size_t)j * FAN + EMB;
    __half* dst = g_w16 + (size_t)rho * HID;
    for (int k = threadIdx.x; k < HID; k += 256)
        dst[k] = __float2half_rn(row[k]);
}

__global__ void gxk(const float* __restrict__ Wf, const float* __restrict__ Wi,
                    const float* __restrict__ Wg, const float* __restrict__ Wo,
                    const float* __restrict__ bf, const float* __restrict__ bi,
                    const float* __restrict__ bg, const float* __restrict__ bo) {
    int rho = blockIdx.x;
    int g = rho >> 11, j = rho & 2047;
    const float* W = (g == 0) ? Wf : (g == 1) ? Wi : (g == 2) ? Wg : Wo;
    const float* B = (g == 0) ? bf : (g == 1) ? bi : (g == 2) ? bg : bo;
    const float* row = W + (size_t)j * FAN;
    __shared__ float wx[EMB];
    for (int k = threadIdx.x; k < EMB; k += 128) wx[k] = row[k];
    __syncthreads();
    int c = threadIdx.x;
    float a0 = 0.f, a1 = 0.f, a2 = 0.f, a3 = 0.f;
    #pragma unroll 4
    for (int k = 0; k < EMB; k += 4) {
        a0 = fmaf(wx[k + 0], g_embT[(size_t)(k + 0) * NCHR + c], a0);
        a1 = fmaf(wx[k + 1], g_embT[(size_t)(k + 1) * NCHR + c], a1);
        a2 = fmaf(wx[k + 2], g_embT[(size_t)(k + 2) * NCHR + c], a2);
        a3 = fmaf(wx[k + 3], g_embT[(size_t)(k + 3) * NCHR + c], a3);
    }
    g_gx[(size_t)c * (4 * HID) + rho] = ((a0 + a1) + (a2 + a3)) + B[j];
}

__global__ void __launch_bounds__(TPB, 1)
lstm_persist(const int* __restrict__ seq, float* __restrict__ d_out) {
    extern __shared__ unsigned char smem[];
    float* s_part = (float*)(smem + PART_OFF);

    uint32_t sbase;
    asm("{ .reg .u64 t; cvta.to.shared.u64 t, %1; cvt.u32.u64 %0, t; }"
        : "=r"(sbase) : "l"(smem));

    const int b   = blockIdx.x;
    const int tid = threadIdx.x;
    const int ne  = (b < 124) ? 14 : 13;
    const int e0  = (b < 124) ? 14 * b : 1736 + 13 * (b - 124);
    const int nrows = 4 * ne;
    const int rows_smem = (nrows < 54) ? nrows : 54;

    // ---- copy fp16 weight rows into smem, 16B-granule XOR swizzle per row
    for (int i = tid; i < rows_smem * 128; i += TPB) {
        int rl = i >> 7, gi = i & 127;                       // gi: 32B granule (uint4=8 halves? no: 16B)
        // use 16B granules: redo with 256 granules per row
        (void)rl; (void)gi;
        break;
    }
    for (int i = tid; i < rows_smem * 256; i += TPB) {
        int rl = i >> 8, gi = i & 255;
        int G = (rl / ne) * HID + e0 + (rl % ne);
        uint4 v = ((const uint4*)(g_w16 + (size_t)G * HID))[gi];
        uint32_t off = rl * 4096 + ((gi * 16) ^ ((rl & 7) << 4));
        *(uint4*)(smem + S_W_OFF + off) = v;
    }

    const int w = tid >> 5, lane = tid & 31;
    const int tile = w >> 3;            // m-tile 0..3 (rows tile*16..)
    const int kc   = w & 7;             // k-chunk: 256 k each

    // ldmatrix lane address components (constant per step)
    int rl_lane = tile * 16 + (lane & 15);
    if (rl_lane >= rows_smem) rl_lane = tile * 16;          // clamp (outputs ignored)
    const uint32_t swz = (uint32_t)((rl_lane & 7) << 4);
    const uint32_t klo16 = (lane >= 16) ? 16u : 0u;
    const uint32_t a_base = sbase + S_W_OFF + (uint32_t)rl_lane * 4096;

    // B-frag source (lanes 0..7 active): col0 lanes 0-3 -> h_hi, col1 lanes 4-7 -> h_lo
    const uint32_t b_off0 = ((lane & 31) < 4 ? HHI_OFF : HLO_OFF) + (uint32_t)kc * 512
                            + (uint32_t)(lane & 3) * 4;

    float scf = 0.f, sci = 0.f, scg = 0.f, sco = 0.f, c_state = 0.f;
    (void)scf; (void)sci; (void)scg; (void)sco;
    __syncthreads();

    for (int t = 0; t < SEQ; t++) {
        // gx prefetch (independent of h -> overlaps the spin)
        float gx0 = 0.f, gx1 = 0.f, gx2 = 0.f, gx3 = 0.f;
        if (tid < ne) {
            int ch = __ldg(seq + t);
            const float* gp = g_gx + (size_t)ch * (4 * HID) + e0 + tid;
            gx0 = __ldg(gp);
            gx1 = __ldg(gp + HID);
            gx2 = __ldg(gp + 2 * HID);
            gx3 = __ldg(gp + 3 * HID);
        }

        if (t > 0) {
            if (tid == 0) {
                unsigned int tgt = (unsigned int)t * NCTA, v;
                do {
                    asm volatile("ld.acquire.gpu.global.u32 %0, [%1];"
                                 : "=r"(v) : "l"(&g_ctr) : "memory");
                } while (v < tgt);
            }
            __syncthreads();
        }

        // ---- stage h: fp32 -> (h_hi, h_lo) fp16 split, once per CTA
        if (tid < 512) {
            float4 v = __ldcv(((const float4*)g_h[t & 1]) + tid);
            __half h0 = __float2half_rn(v.x), h1 = __float2half_rn(v.y);
            __half h2 = __float2half_rn(v.z), h3 = __float2half_rn(v.w);
            __half l0 = __float2half_rn(v.x - __half2float(h0));
            __half l1 = __float2half_rn(v.y - __half2float(h1));
            __half l2 = __float2half_rn(v.z - __half2float(h2));
            __half l3 = __float2half_rn(v.w - __half2float(h3));
            uint2 hi = make_uint2(pack_h2(h0, h1), pack_h2(h2, h3));
            uint2 lo = make_uint2(pack_h2(l0, l1), pack_h2(l2, l3));
            *(uint2*)(smem + HHI_OFF + tid * 8) = hi;
            *(uint2*)(smem + HLO_OFF + tid * 8) = lo;
        }
        __syncthreads();

        // ---- HMMA mainloop: 16 k-tiles of k16, accumulate fp32
        float c0 = 0.f, c1 = 0.f, c2 = 0.f, c3 = 0.f;
        uint32_t bb0 = 0u, bb1 = 0u;
        #pragma unroll
        for (int kt = 0; kt < 16; kt++) {
            uint32_t byt = (uint32_t)(kc * 512 + kt * 32) + klo16;
            uint32_t a_addr = a_base + (byt ^ swz);
            uint32_t a0, a1, a2, a3;
            asm volatile("ldmatrix.sync.aligned.m8n8.x4.shared.b16 {%0,%1,%2,%3}, [%4];"
                         : "=r"(a0), "=r"(a1), "=r"(a2), "=r"(a3) : "r"(a_addr));
            if (lane < 8) {
                bb0 = *(const uint32_t*)(smem + b_off0 + kt * 32);
                bb1 = *(const uint32_t*)(smem + b_off0 + kt * 32 + 16);
            }
            asm volatile("mma.sync.aligned.m16n8k16.row.col.f32.f16.f16.f32 "
                         "{%0,%1,%2,%3}, {%4,%5,%6,%7}, {%8,%9}, {%0,%1,%2,%3};"
                         : "+f"(c0), "+f"(c1), "+f"(c2), "+f"(c3)
                         : "r"(a0), "r"(a1), "r"(a2), "r"(a3), "r"(bb0), "r"(bb1));
        }

        // ---- extract: lanes l%4==0 hold cols 0,1 -> partial = w.h_hi + w.h_lo
        if ((lane & 3) == 0) {
            int r0 = tile * 16 + (lane >> 2);
            int r1 = r0 + 8;
            if (r0 < rows_smem) s_part[tile * 128 + kc * 16 + (lane >> 2)] = c0 + c1;
            if (r1 < rows_smem) s_part[tile * 128 + kc * 16 + (lane >> 2) + 8] = c2 + c3;
        }

        // ---- overflow rows 54,55 (ne==14 only): fp16-w FFMA from gmem, h = hi+lo
        if (ne == 14 && tile == 3) {
            int k0 = kc * 256 + lane * 8;
            uint4 hh = *(const uint4*)(smem + HHI_OFF + k0 * 2);
            uint4 hl = *(const uint4*)(smem + HLO_OFF + k0 * 2);
            float2 hf0 = h22f2(hh.x), hf1 = h22f2(hh.y), hf2 = h22f2(hh.z), hf3 = h22f2(hh.w);
            float2 lf0 = h22f2(hl.x), lf1 = h22f2(hl.y), lf2 = h22f2(hl.z), lf3 = h22f2(hl.w);
            hf0.x += lf0.x; hf0.y += lf0.y; hf1.x += lf1.x; hf1.y += lf1.y;
            hf2.x += lf2.x; hf2.y += lf2.y; hf3.x += lf3.x; hf3.y += lf3.y;
            #pragma unroll
            for (int rr = 0; rr < 2; rr++) {
                const uint4* wp = (const uint4*)(g_w16 + (size_t)(3 * HID + e0 + 12 + rr) * HID + k0);
                uint4 wv = __ldg(wp);
                float2 w0 = h22f2(wv.x), w1 = h22f2(wv.y), w2 = h22f2(wv.z), w3 = h22f2(wv.w);
                float acc = w0.x * hf0.x;
                acc = fmaf(w0.y, hf0.y, acc);
                acc = fmaf(w1.x, hf1.x, acc);
                acc = fmaf(w1.y, hf1.y, acc);
                acc = fmaf(w2.x, hf2.x, acc);
                acc = fmaf(w2.y, hf2.y, acc);
                acc = fmaf(w3.x, hf3.x, acc);
                acc = fmaf(w3.y, hf3.y, acc);
                #pragma unroll
                for (int o = 16; o > 0; o >>= 1)
                    acc += __shfl_xor_sync(0xffffffffu, acc, o);
                if (lane == 0) s_part[3 * 128 + kc * 16 + 6 + rr] = acc;
            }
        }
        __syncthreads();

        // ---- combine: sum 8 k-chunks per row, activations, write h/c/hist
        if (tid < ne) {
            float p[4];
            #pragma unroll
            for (int g = 0; g < 4; g++) {
                int rl = g * ne + tid;
                const float* sp = s_part + (rl >> 4) * 128 + (rl & 15);
                float s = 0.f;
                #pragma unroll
                for (int k = 0; k < 8; k++) s += sp[k * 16];
                p[g] = s;
            }
            float fg = sigf(p[0] + gx0);
            float ig = sigf(p[1] + gx1);
            float gg = tanh_f(p[2] + gx2);
            float og = sigf(p[3] + gx3);
            c_state = fg * c_state + ig * gg;
            float hnew = og * tanh_f(c_state);
            int jj = e0 + tid;
            __stcg(&g_h[(t + 1) & 1][jj], hnew);
            g_hist[(size_t)t * HID + jj] = hnew;
            if (t == SEQ - 1) {
                d_out[(size_t)SEQ * NCHR + jj] = hnew;
                d_out[(size_t)SEQ * NCHR + HID + jj] = c_state;
            }
        }
        __syncthreads();
        if (tid == 0)
            asm volatile("red.release.gpu.global.add.u32 [%0], %1;"
                         :: "l"(&g_ctr), "r"(1u) : "memory");
    }
}

__global__ void __launch_bounds__(128)
logitsk(const float* __restrict__ Wfc, const float* __restrict__ bfc,
        float* __restrict__ out) {
    __shared__ float hs[16][129];
    const int t0 = blockIdx.x * 16;
    const int c = threadIdx.x;
    float acc[16];
    float bias = bfc[c];
    #pragma unroll
    for (int i = 0; i < 16; i++) acc[i] = bias;

    for (int k0 = 0; k0 < HID; k0 += 128) {
        __syncthreads();
        #pragma unroll
        for (int i = 0; i < 16; i++)
            hs[i][c] = g_hist[(size_t)(t0 + i) * HID + k0 + c];
        __syncthreads();
        #pragma unroll 4
        for (int kk = 0; kk < 128; kk++) {
            float wv = __ldg(Wfc + (size_t)c * HID + k0 + kk);
            #pragma unroll
            for (int i = 0; i < 16; i++)
                acc[i] = fmaf(hs[i][kk], wv, acc[i]);
        }
    }
    #pragma unroll
    for (int i = 0; i < 16; i++)
        out[(size_t)(t0 + i) * NCHR + c] = acc[i];
}

extern "C" void kernel_launch(void* const* d_in, const int* in_sizes, int n_in,
                              void* d_out, int out_size) {
    const int*   seq = (const int*)d_in[0];
    const float* emb = (const float*)d_in[1];
    const float* Wf  = (const float*)d_in[2];
    const float* bf  = (const float*)d_in[3];
    const float* Wi  = (const float*)d_in[4];
    const float* bi  = (const float*)d_in[5];
    const float* Wg  = (const float*)d_in[6];
    const float* bg  = (const float*)d_in[7];
    const float* Wo  = (const float*)d_in[8];
    const float* bo  = (const float*)d_in[9];
    const float* Wfc = (const float*)d_in[10];
    const float* bfc = (const float*)d_in[11];
    float* out = (float*)d_out;

    cudaFuncSetAttribute(lstm_persist,
                         cudaFuncAttributeMaxDynamicSharedMemorySize, SMEM_BYTES);

    embTk<<<(EMB * NCHR + 255) / 256, 256>>>(emb);                    // launch 0
    w16k<<<4 * HID, 256>>>(Wf, Wi, Wg, Wo);                           // launch 1 (+reset)
    gxk<<<4 * HID, 128>>>(Wf, Wi, Wg, Wo, bf, bi, bg, bo);            // launch 2
    lstm_persist<<<NCTA, TPB, SMEM_BYTES>>>(seq, out);                // launch 3 (ncu slot)
    logitsk<<<SEQ / 16, 128>>>(Wfc, bfc, out);                        // launch 4
}